// round 4
// baseline (speedup 1.0000x reference)
#include <cuda_runtime.h>
#include <cuda_bf16.h>
#include <math.h>
#include <stdint.h>

#define Bb 4
#define Ss 1024
#define Dd 1024
#define Hh 16
#define HD 64
#define BHt (Bb*Hh)
#define Mrows (Bb*Ss)

// ---------------- device scratch ----------------
__device__ __nv_bfloat16 g_qh[(size_t)Mrows*Dd];
__device__ __nv_bfloat16 g_ql[(size_t)Mrows*Dd];
__device__ __nv_bfloat16 g_kh[(size_t)Mrows*Dd];
__device__ __nv_bfloat16 g_kl[(size_t)Mrows*Dd];
__device__ __nv_bfloat16 g_vh[(size_t)Mrows*Dd];
__device__ __nv_bfloat16 g_vl[(size_t)Mrows*Dd];
__device__ float g_x[(size_t)Mrows*Dd];
__device__ float g_p_fallback[(size_t)BHt*Ss*Ss];

// ---------------- helpers ----------------
__device__ __forceinline__ uint32_t smem_u32(const void* p) {
    uint32_t a;
    asm("{ .reg .u64 t; cvta.to.shared.u64 t, %1; cvt.u32.u64 %0, t; }" : "=r"(a) : "l"(p));
    return a;
}
__device__ __forceinline__ void ldsm_x4(uint32_t* r, uint32_t addr) {
    asm volatile("ldmatrix.sync.aligned.m8n8.x4.shared.b16 {%0,%1,%2,%3}, [%4];"
                 : "=r"(r[0]), "=r"(r[1]), "=r"(r[2]), "=r"(r[3]) : "r"(addr));
}
__device__ __forceinline__ void ldsm_x2t(uint32_t* r, uint32_t addr) {
    asm volatile("ldmatrix.sync.aligned.m8n8.x2.trans.shared.b16 {%0,%1}, [%2];"
                 : "=r"(r[0]), "=r"(r[1]) : "r"(addr));
}
__device__ __forceinline__ void mma16816(float* c, const uint32_t* a, const uint32_t* b) {
    asm volatile(
        "mma.sync.aligned.m16n8k16.row.col.f32.bf16.bf16.f32 "
        "{%0,%1,%2,%3}, {%4,%5,%6,%7}, {%8,%9}, {%0,%1,%2,%3};"
        : "+f"(c[0]), "+f"(c[1]), "+f"(c[2]), "+f"(c[3])
        : "r"(a[0]), "r"(a[1]), "r"(a[2]), "r"(a[3]), "r"(b[0]), "r"(b[1]));
}
__device__ __forceinline__ void split2(float x, float y, uint32_t& h, uint32_t& l) {
    __nv_bfloat16 hx = __float2bfloat16_rn(x);
    __nv_bfloat16 hy = __float2bfloat16_rn(y);
    __nv_bfloat162 hp; hp.x = hx; hp.y = hy;
    __nv_bfloat162 lp;
    lp.x = __float2bfloat16_rn(x - __bfloat162float(hx));
    lp.y = __float2bfloat16_rn(y - __bfloat162float(hy));
    h = *(uint32_t*)&hp;
    l = *(uint32_t*)&lp;
}
__device__ __forceinline__ void split8(const float4 a, const float4 b, uint4& h, uint4& l) {
    split2(a.x, a.y, h.x, l.x);
    split2(a.z, a.w, h.y, l.y);
    split2(b.x, b.y, h.z, l.z);
    split2(b.z, b.w, h.w, l.w);
}

// --------- 128x128 GEMM: fp32 in, in-kernel hi/lo split, 3-term MMA ---------
__global__ __launch_bounds__(256) void gemm_f32_tc(
    const float* __restrict__ A, const float* __restrict__ W,
    const float* __restrict__ bias,
    float* __restrict__ Cf, __nv_bfloat16* __restrict__ Ch,
    __nv_bfloat16* __restrict__ Cl, int mode,
    int Mn, int Nn, int Kn)
{
    __shared__ __align__(16) __nv_bfloat16 As[128][64];
    __shared__ __align__(16) __nv_bfloat16 Bs[2][32][128];

    const int tid = threadIdx.x;
    const int warp = tid >> 5, lane = tid & 31;
    const int wm = (warp >> 2) << 6;
    const int wn = (warp & 3) << 5;
    const int bm = blockIdx.y << 7, bn = blockIdx.x << 7;

    const uint32_t as0 = smem_u32(&As[0][0]);
    const uint32_t bs0 = smem_u32(&Bs[0][0][0]);

    float acc[4][4][4];
#pragma unroll
    for (int i = 0; i < 4; i++)
#pragma unroll
        for (int j = 0; j < 4; j++)
#pragma unroll
            for (int r = 0; r < 4; r++) acc[i][j][r] = 0.f;

    const int arow = tid >> 1, acol = (tid & 1) << 4;
    const float* gA = A + (size_t)(bm + arow) * Kn + acol;
    const int bk = tid >> 3, bcol = (tid & 7) << 4;
    const float* gW = W + (size_t)bk * Nn + bn + bcol;

    char* apB = (char*)(&As[0][0]) + arow * 128;
    char* bpB = (char*)(&Bs[0][0][0]) + bk * 256;
    const int swa = arow & 7, swb = bk & 7;
    const int ac0 = (tid & 1) << 1;
    const int bc0 = (tid & 7) << 1;

    for (int k0 = 0; k0 < Kn; k0 += 32) {
        float4 fa0 = *(const float4*)(gA + k0);
        float4 fa1 = *(const float4*)(gA + k0 + 4);
        float4 fa2 = *(const float4*)(gA + k0 + 8);
        float4 fa3 = *(const float4*)(gA + k0 + 12);
        float4 fw0 = *(const float4*)(gW + (size_t)k0 * Nn);
        float4 fw1 = *(const float4*)(gW + (size_t)k0 * Nn + 4);
        float4 fw2 = *(const float4*)(gW + (size_t)k0 * Nn + 8);
        float4 fw3 = *(const float4*)(gW + (size_t)k0 * Nn + 12);
        uint4 ah0, al0, ah1, al1, wh0, wl0, wh1, wl1;
        split8(fa0, fa1, ah0, al0);
        split8(fa2, fa3, ah1, al1);
        split8(fw0, fw1, wh0, wl0);
        split8(fw2, fw3, wh1, wl1);
        __syncthreads();
        *(uint4*)(apB + (((ac0 | 0) ^ swa) << 4)) = ah0;
        *(uint4*)(apB + (((ac0 | 1) ^ swa) << 4)) = ah1;
        *(uint4*)(apB + ((((ac0 | 0) + 4) ^ swa) << 4)) = al0;
        *(uint4*)(apB + ((((ac0 | 1) + 4) ^ swa) << 4)) = al1;
        *(uint4*)(bpB + (((bc0 | 0) ^ swb) << 4)) = wh0;
        *(uint4*)(bpB + (((bc0 | 1) ^ swb) << 4)) = wh1;
        *(uint4*)(bpB + 8192 + (((bc0 | 0) ^ swb) << 4)) = wl0;
        *(uint4*)(bpB + 8192 + (((bc0 | 1) ^ swb) << 4)) = wl1;
        __syncthreads();

#pragma unroll
        for (int ks = 0; ks < 2; ks++) {
            uint32_t af[2][4][4];
            uint32_t bf[2][4][2];
            const int r15 = lane & 15;
            const int choff = (ks << 1) + (lane >> 4);
#pragma unroll
            for (int mf = 0; mf < 4; mf++) {
                int row = wm + (mf << 4) + r15;
                uint32_t base = as0 + row * 128;
                int sw = row & 7;
                ldsm_x4(af[0][mf], base + ((choff ^ sw) << 4));
                ldsm_x4(af[1][mf], base + (((choff + 4) ^ sw) << 4));
            }
            const int krow = (ks << 4) + r15;
            const int swk = krow & 7;
#pragma unroll
            for (int nf = 0; nf < 4; nf++) {
                int chunk = (wn + (nf << 3)) >> 3;
                uint32_t ad = bs0 + krow * 256 + ((chunk ^ swk) << 4);
                ldsm_x2t(bf[0][nf], ad);
                ldsm_x2t(bf[1][nf], ad + 8192);
            }
#pragma unroll
            for (int mf = 0; mf < 4; mf++)
#pragma unroll
                for (int nf = 0; nf < 4; nf++) {
                    mma16816(acc[mf][nf], af[0][mf], bf[0][nf]);
                    mma16816(acc[mf][nf], af[0][mf], bf[1][nf]);
                    mma16816(acc[mf][nf], af[1][mf], bf[0][nf]);
                }
        }
    }

    const int gr = lane >> 2, gc = (lane & 3) << 1;
#pragma unroll
    for (int mf = 0; mf < 4; mf++) {
        int r0 = bm + wm + (mf << 4) + gr;
#pragma unroll
        for (int nf = 0; nf < 4; nf++) {
            int col = bn + wn + (nf << 3) + gc;
            float2 bv = *(const float2*)(bias + col);
            float c00 = acc[mf][nf][0] + bv.x, c01 = acc[mf][nf][1] + bv.y;
            float c10 = acc[mf][nf][2] + bv.x, c11 = acc[mf][nf][3] + bv.y;
            if (mode == 0) {
                *(float2*)(Cf + (size_t)r0 * Nn + col) = make_float2(c00, c01);
                *(float2*)(Cf + (size_t)(r0 + 8) * Nn + col) = make_float2(c10, c11);
            } else {
                uint32_t h, l;
                split2(c00, c01, h, l);
                *(uint32_t*)(Ch + (size_t)r0 * Nn + col) = h;
                *(uint32_t*)(Cl + (size_t)r0 * Nn + col) = l;
                split2(c10, c11, h, l);
                *(uint32_t*)(Ch + (size_t)(r0 + 8) * Nn + col) = h;
                *(uint32_t*)(Cl + (size_t)(r0 + 8) * Nn + col) = l;
            }
        }
    }
}

// ===== fused two-pass attention: rowsums, then normalized P + X=P@V =====
// dynamic smem layout (bytes):
//   Qh 0, Ql 8192, Kh 16384, Kl 24576, Vh 32768, Vl 40960, Ph 49152, Pl 57344,
//   sinv 65536 (256), red 65792 (1024), msk 66816 (4096)  -> total 70912
#define SM_QH 0
#define SM_QL 8192
#define SM_KH 16384
#define SM_KL 24576
#define SM_VH 32768
#define SM_VL 40960
#define SM_PH 49152
#define SM_PL 57344
#define SM_SINV 65536
#define SM_RED 65792
#define SM_MSK 66816
#define SM_TOTAL 70912

__global__ __launch_bounds__(256) void attn_fused(
    const __nv_bfloat16* __restrict__ qh, const __nv_bfloat16* __restrict__ ql,
    const __nv_bfloat16* __restrict__ kh, const __nv_bfloat16* __restrict__ kl,
    const __nv_bfloat16* __restrict__ vh, const __nv_bfloat16* __restrict__ vl,
    const int* __restrict__ mask, float* __restrict__ P, float* __restrict__ X)
{
    extern __shared__ __align__(16) char sm[];
    float* sinv = (float*)(sm + SM_SINV);
    float (*red)[4] = (float(*)[4])(sm + SM_RED);
    int* msk = (int*)(sm + SM_MSK);

    const int tid = threadIdx.x;
    const int warp = tid >> 5, lane = tid & 31;
    const int wm = (warp >> 2) << 5;
    const int wn = (warp & 3) << 4;
    const int bh = blockIdx.y;
    const int b = bh >> 4, h = bh & 15;
    const int q0 = blockIdx.x << 6;

    const uint32_t smb = smem_u32(sm);
    const uint32_t qh0 = smb + SM_QH, ql0 = smb + SM_QL;
    const uint32_t kh0 = smb + SM_KH, kl0 = smb + SM_KL;
    const uint32_t vh0 = smb + SM_VH, vl0 = smb + SM_VL;
    const uint32_t ph0 = smb + SM_PH, pl0 = smb + SM_PL;

    // mask into smem
#pragma unroll
    for (int i = 0; i < 4; i++)
        msk[tid + (i << 8)] = mask[b * Ss + tid + (i << 8)];

    // Q tile
    {
        int row = tid >> 2;
        int c0 = (tid & 3) << 1;
        const size_t base = ((size_t)(b * Ss + q0 + row)) * Dd + h * HD;
#pragma unroll
        for (int i = 0; i < 2; i++) {
            int c = c0 + i;
            int swc = ((c ^ (row & 7)) << 4) + row * 128;
            *(uint4*)(sm + SM_QH + swc) = *(const uint4*)(qh + base + (c << 3));
            *(uint4*)(sm + SM_QL + swc) = *(const uint4*)(ql + base + (c << 3));
        }
    }

    const int gr = lane >> 2, gc = (lane & 3) << 1;
    const int r15 = lane & 15;
    const float sc = 0.125f;

    // ---------------- pass 1: rowsums ----------------
    float rs[2][2] = {{0.f, 0.f}, {0.f, 0.f}};
    for (int kt = 0; kt < 16; kt++) {
        const int k0 = kt << 6;
        __syncthreads();
        {
            int row = tid >> 2;
            int c0 = (tid & 3) << 1;
            const size_t base = ((size_t)(b * Ss + k0 + row)) * Dd + h * HD;
#pragma unroll
            for (int i = 0; i < 2; i++) {
                int c = c0 + i;
                int swc = ((c ^ (row & 7)) << 4) + row * 128;
                *(uint4*)(sm + SM_KH + swc) = *(const uint4*)(kh + base + (c << 3));
                *(uint4*)(sm + SM_KL + swc) = *(const uint4*)(kl + base + (c << 3));
            }
        }
        __syncthreads();

        float eacc[2][2][4];
#pragma unroll
        for (int i = 0; i < 2; i++)
#pragma unroll
            for (int j = 0; j < 2; j++)
#pragma unroll
                for (int r = 0; r < 4; r++) eacc[i][j][r] = 0.f;

#pragma unroll
        for (int ks = 0; ks < 4; ks++) {
            const int choff = (ks << 1) + (lane >> 4);
            uint32_t aH[2][4], aL[2][4];
#pragma unroll
            for (int mf = 0; mf < 2; mf++) {
                int row = wm + (mf << 4) + r15;
                int off = row * 128 + ((choff ^ (row & 7)) << 4);
                ldsm_x4(aH[mf], qh0 + off);
                ldsm_x4(aL[mf], ql0 + off);
            }
            int nrow = wn + ((lane >> 4) << 3) + (lane & 7);
            int kch = (ks << 1) + ((lane >> 3) & 1);
            int boff = nrow * 128 + ((kch ^ (nrow & 7)) << 4);
            uint32_t bH[4], bL[4];
            ldsm_x4(bH, kh0 + boff);
            ldsm_x4(bL, kl0 + boff);
#pragma unroll
            for (int mf = 0; mf < 2; mf++)
#pragma unroll
                for (int nf = 0; nf < 2; nf++) {
                    mma16816(eacc[mf][nf], aH[mf], bH + nf * 2);
                    mma16816(eacc[mf][nf], aH[mf], bL + nf * 2);
                    mma16816(eacc[mf][nf], aL[mf], bH + nf * 2);
                }
        }

#pragma unroll
        for (int mf = 0; mf < 2; mf++)
#pragma unroll
            for (int nf = 0; nf < 2; nf++) {
                int col = k0 + wn + (nf << 3) + gc;
                int m0 = msk[col], m1 = msk[col + 1];
                rs[mf][0] += (m0 ? __expf(eacc[mf][nf][0] * sc) : 0.f)
                           + (m1 ? __expf(eacc[mf][nf][1] * sc) : 0.f);
                rs[mf][1] += (m0 ? __expf(eacc[mf][nf][2] * sc) : 0.f)
                           + (m1 ? __expf(eacc[mf][nf][3] * sc) : 0.f);
            }
    }

    // reduce rowsums -> sinv
#pragma unroll
    for (int mf = 0; mf < 2; mf++)
#pragma unroll
        for (int hf = 0; hf < 2; hf++) {
            float v = rs[mf][hf];
            v += __shfl_xor_sync(0xffffffff, v, 1);
            v += __shfl_xor_sync(0xffffffff, v, 2);
            if ((lane & 3) == 0)
                red[wm + (mf << 4) + gr + (hf << 3)][warp & 3] = v;
        }
    __syncthreads();
    if (tid < 64)
        sinv[tid] = 1.0f / (red[tid][0] + red[tid][1] + red[tid][2] + red[tid][3]);
    __syncthreads();

    float iv[2][2];
#pragma unroll
    for (int mf = 0; mf < 2; mf++) {
        iv[mf][0] = sinv[wm + (mf << 4) + gr];
        iv[mf][1] = sinv[wm + (mf << 4) + gr + 8];
    }

    // ---------------- pass 2: normalized P + X = P@V ----------------
    float xacc[2][2][4];
#pragma unroll
    for (int i = 0; i < 2; i++)
#pragma unroll
        for (int j = 0; j < 2; j++)
#pragma unroll
            for (int r = 0; r < 4; r++) xacc[i][j][r] = 0.f;

    for (int kt = 0; kt < 16; kt++) {
        const int k0 = kt << 6;
        __syncthreads();
        {
            int row = tid >> 2;
            int c0 = (tid & 3) << 1;
            const size_t base = ((size_t)(b * Ss + k0 + row)) * Dd + h * HD;
#pragma unroll
            for (int i = 0; i < 2; i++) {
                int c = c0 + i;
                int swc = ((c ^ (row & 7)) << 4) + row * 128;
                *(uint4*)(sm + SM_KH + swc) = *(const uint4*)(kh + base + (c << 3));
                *(uint4*)(sm + SM_KL + swc) = *(const uint4*)(kl + base + (c << 3));
                *(uint4*)(sm + SM_VH + swc) = *(const uint4*)(vh + base + (c << 3));
                *(uint4*)(sm + SM_VL + swc) = *(const uint4*)(vl + base + (c << 3));
            }
        }
        __syncthreads();

        float eacc[2][2][4];
#pragma unroll
        for (int i = 0; i < 2; i++)
#pragma unroll
            for (int j = 0; j < 2; j++)
#pragma unroll
                for (int r = 0; r < 4; r++) eacc[i][j][r] = 0.f;

#pragma unroll
        for (int ks = 0; ks < 4; ks++) {
            const int choff = (ks << 1) + (lane >> 4);
            uint32_t aH[2][4], aL[2][4];
#pragma unroll
            for (int mf = 0; mf < 2; mf++) {
                int row = wm + (mf << 4) + r15;
                int off = row * 128 + ((choff ^ (row & 7)) << 4);
                ldsm_x4(aH[mf], qh0 + off);
                ldsm_x4(aL[mf], ql0 + off);
            }
            int nrow = wn + ((lane >> 4) << 3) + (lane & 7);
            int kch = (ks << 1) + ((lane >> 3) & 1);
            int boff = nrow * 128 + ((kch ^ (nrow & 7)) << 4);
            uint32_t bH[4], bL[4];
            ldsm_x4(bH, kh0 + boff);
            ldsm_x4(bL, kl0 + boff);
#pragma unroll
            for (int mf = 0; mf < 2; mf++)
#pragma unroll
                for (int nf = 0; nf < 2; nf++) {
                    mma16816(eacc[mf][nf], aH[mf], bH + nf * 2);
                    mma16816(eacc[mf][nf], aH[mf], bL + nf * 2);
                    mma16816(eacc[mf][nf], aL[mf], bH + nf * 2);
                }
        }

        // epilogue: normalize, write P, stash bf16 split into smem
#pragma unroll
        for (int mf = 0; mf < 2; mf++) {
            int lr0 = wm + (mf << 4) + gr;
            int row0 = q0 + lr0;
#pragma unroll
            for (int nf = 0; nf < 2; nf++) {
                int lcol = wn + (nf << 3) + gc;
                int col = k0 + lcol;
                int m0 = msk[col], m1 = msk[col + 1];
                float e0 = m0 ? __expf(eacc[mf][nf][0] * sc) * iv[mf][0] : 0.f;
                float e1 = m1 ? __expf(eacc[mf][nf][1] * sc) * iv[mf][0] : 0.f;
                float e2 = m0 ? __expf(eacc[mf][nf][2] * sc) * iv[mf][1] : 0.f;
                float e3 = m1 ? __expf(eacc[mf][nf][3] * sc) * iv[mf][1] : 0.f;
                *(float2*)(P + ((size_t)bh * Ss + row0) * Ss + col) = make_float2(e0, e1);
                *(float2*)(P + ((size_t)bh * Ss + row0 + 8) * Ss + col) = make_float2(e2, e3);
                int chunk = lcol >> 3;
                uint32_t hp, lp;
                split2(e0, e1, hp, lp);
                int o0 = lr0 * 128 + ((chunk ^ (lr0 & 7)) << 4) + ((lcol & 7) << 1);
                *(uint32_t*)(sm + SM_PH + o0) = hp;
                *(uint32_t*)(sm + SM_PL + o0) = lp;
                split2(e2, e3, hp, lp);
                int lr1 = lr0 + 8;
                int o1 = lr1 * 128 + ((chunk ^ (lr1 & 7)) << 4) + ((lcol & 7) << 1);
                *(uint32_t*)(sm + SM_PH + o1) = hp;
                *(uint32_t*)(sm + SM_PL + o1) = lp;
            }
        }
        __syncthreads();

        // X += P @ V
#pragma unroll
        for (int ks = 0; ks < 4; ks++) {
            const int choff = (ks << 1) + (lane >> 4);
            uint32_t aH[2][4], aL[2][4];
#pragma unroll
            for (int mf = 0; mf < 2; mf++) {
                int row = wm + (mf << 4) + r15;
                int off = row * 128 + ((choff ^ (row & 7)) << 4);
                ldsm_x4(aH[mf], ph0 + off);
                ldsm_x4(aL[mf], pl0 + off);
            }
            const int krow = (ks << 4) + r15;
            const int swk = krow & 7;
            uint32_t bH[2][2], bL[2][2];
#pragma unroll
            for (int nf = 0; nf < 2; nf++) {
                int chunk = (wn + (nf << 3)) >> 3;
                int boff = krow * 128 + ((chunk ^ swk) << 4);
                ldsm_x2t(bH[nf], vh0 + boff);
                ldsm_x2t(bL[nf], vl0 + boff);
            }
#pragma unroll
            for (int mf = 0; mf < 2; mf++)
#pragma unroll
                for (int nf = 0; nf < 2; nf++) {
                    mma16816(xacc[mf][nf], aH[mf], bH[nf]);
                    mma16816(xacc[mf][nf], aH[mf], bL[nf]);
                    mma16816(xacc[mf][nf], aL[mf], bH[nf]);
                }
        }
    }

    // write X
#pragma unroll
    for (int mf = 0; mf < 2; mf++) {
        int row0 = q0 + wm + (mf << 4) + gr;
#pragma unroll
        for (int nf = 0; nf < 2; nf++) {
            int col = h * HD + wn + (nf << 3) + gc;
            *(float2*)(X + ((size_t)(b * Ss + row0)) * Dd + col) =
                make_float2(xacc[mf][nf][0], xacc[mf][nf][1]);
            *(float2*)(X + ((size_t)(b * Ss + row0 + 8)) * Dd + col) =
                make_float2(xacc[mf][nf][2], xacc[mf][nf][3]);
        }
    }
}

// ---------------- launch ----------------
extern "C" void kernel_launch(void* const* d_in, const int* in_sizes, int n_in,
                              void* d_out, int out_size)
{
    const float* query = (const float*)d_in[0];
    const float* key   = (const float*)d_in[1];
    const float* value = (const float*)d_in[2];
    const int*   mask  = (const int*)d_in[3];
    const float* Wq = (const float*)d_in[4];  const float* bq = (const float*)d_in[5];
    const float* Wk = (const float*)d_in[6];  const float* bk = (const float*)d_in[7];
    const float* Wv = (const float*)d_in[8];  const float* bv = (const float*)d_in[9];
    const float* Wo = (const float*)d_in[10]; const float* bo = (const float*)d_in[11];

    float* out = (float*)d_out;
    const size_t BSD = (size_t)Bb * Ss * Dd;
    const size_t ATT = (size_t)BHt * Ss * Ss;

    void *pqh, *pql, *pkh, *pkl, *pvh, *pvl, *px;
    cudaGetSymbolAddress(&pqh, g_qh);
    cudaGetSymbolAddress(&pql, g_ql);
    cudaGetSymbolAddress(&pkh, g_kh);
    cudaGetSymbolAddress(&pkl, g_kl);
    cudaGetSymbolAddress(&pvh, g_vh);
    cudaGetSymbolAddress(&pvl, g_vl);
    cudaGetSymbolAddress(&px, g_x);
    __nv_bfloat16* qh = (__nv_bfloat16*)pqh;
    __nv_bfloat16* ql = (__nv_bfloat16*)pql;
    __nv_bfloat16* kh = (__nv_bfloat16*)pkh;
    __nv_bfloat16* kl = (__nv_bfloat16*)pkl;
    __nv_bfloat16* vh = (__nv_bfloat16*)pvh;
    __nv_bfloat16* vl = (__nv_bfloat16*)pvl;
    float* x = (float*)px;

    float* P;
    if ((size_t)out_size >= BSD + ATT) {
        P = out + BSD;
    } else {
        void* pp;
        cudaGetSymbolAddress(&pp, g_p_fallback);
        P = (float*)pp;
    }

    static int smem_set = 0;
    if (!smem_set) {
        cudaFuncSetAttribute(attn_fused,
                             cudaFuncAttributeMaxDynamicSharedMemorySize, SM_TOTAL);
        smem_set = 1;
    }

    dim3 gemm_grid(Dd / 128, Mrows / 128);  // (8, 32)

    gemm_f32_tc<<<gemm_grid, 256>>>(query, Wq, bq, nullptr, qh, ql, 1, Mrows, Dd, Dd);
    gemm_f32_tc<<<gemm_grid, 256>>>(key,   Wk, bk, nullptr, kh, kl, 1, Mrows, Dd, Dd);
    gemm_f32_tc<<<gemm_grid, 256>>>(value, Wv, bv, nullptr, vh, vl, 1, Mrows, Dd, Dd);

    attn_fused<<<dim3(Ss / 64, BHt), 256, SM_TOTAL>>>(qh, ql, kh, kl, vh, vl, mask, P, x);

    gemm_f32_tc<<<gemm_grid, 256>>>(x, Wo, bo, out, nullptr, nullptr, 0, Mrows, Dd, Dd);
}